// round 8
// baseline (speedup 1.0000x reference)
#include <cuda_runtime.h>
#include <cstdint>

#define COLS 16384
#define KSEL 256
#define NT   512
#define CAP  2048
#define WCAP 512

typedef unsigned long long u64;

__global__ void __launch_bounds__(NT, 3)
topk_kernel(const float* __restrict__ x, float* __restrict__ out)
{
    __shared__ u64 cand[CAP];
    __shared__ u64 slist[WCAP];
    __shared__ unsigned hist[256];
    __shared__ unsigned S[8];   // 0:cnt 2:m 3:jbin 4:nab 5:cnt_in

    const int tid = threadIdx.x, lane = tid & 31, wid = tid >> 5;
    const size_t row = blockIdx.x;
    const float4* __restrict__ xr4 = (const float4*)(x + row * COLS);
    float* __restrict__ orow = out + row * COLS;
    float4* __restrict__ orow4 = (float4*)orow;

    if (tid < 256) hist[tid] = 0;
    if (tid == 0) { S[0] = 0; S[2] = 0; }

    // ---- zero-fill output row first: no deps, write traffic drains during reads ----
    float4 z = make_float4(0.f, 0.f, 0.f, 0.f);
    #pragma unroll
    for (int i = 0; i < 8; i++) orow4[tid + i * NT] = z;
    __syncthreads();

    // ---- pass 1: stream row in 2 chunks, push candidates >= T into smem list ----
    unsigned kT = 0x3FF33333u;            // bits(1.9f): ~470 expected for N(0,1)
    unsigned C = 0;
    unsigned aLo = 0u, bHi = 0x7F800001u; // positive-bits search interval
    for (int att = 0; att < 34; att++) {
        const float Tf = __uint_as_float(kT);
        #pragma unroll
        for (int ch = 0; ch < 2; ch++) {
            float4 t[4];
            #pragma unroll
            for (int c = 0; c < 4; c++) t[c] = xr4[tid + (ch * 4 + c) * NT];
            #pragma unroll
            for (int c = 0; c < 4; c++) {
                unsigned idx0 = 4u * (unsigned)(tid + (ch * 4 + c) * NT);
                float f0 = t[c].x, f1 = t[c].y, f2 = t[c].z, f3 = t[c].w;
                if (f0 >= Tf) { unsigned p = atomicAdd(&S[0], 1u); if (p < CAP) cand[p] = ((u64)__float_as_uint(f0) << 32) | (unsigned)~(idx0);      }
                if (f1 >= Tf) { unsigned p = atomicAdd(&S[0], 1u); if (p < CAP) cand[p] = ((u64)__float_as_uint(f1) << 32) | (unsigned)~(idx0 + 1u); }
                if (f2 >= Tf) { unsigned p = atomicAdd(&S[0], 1u); if (p < CAP) cand[p] = ((u64)__float_as_uint(f2) << 32) | (unsigned)~(idx0 + 2u); }
                if (f3 >= Tf) { unsigned p = atomicAdd(&S[0], 1u); if (p < CAP) cand[p] = ((u64)__float_as_uint(f3) << 32) | (unsigned)~(idx0 + 3u); }
            }
        }
        __syncthreads();
        C = S[0];
        if (C >= KSEL && C <= CAP) break;      // happy path: first attempt
        if (C > CAP) aLo = kT; else bHi = kT;  // rare fallback: rows are L2-hot
        unsigned nkT = aLo + ((bHi - aLo) >> 1);
        if (nkT == kT || nkT == 0u) break;     // collapsed: C<KSEL -> all positives win
        kT = nkT;
        __syncthreads();
        if (tid == 0) S[0] = 0;
        __syncthreads();
    }
    if (C > CAP) C = CAP;
    unsigned need = (KSEL < C) ? KSEL : C;

    // ---- narrowing over the candidate LIST (bits-space 256-bin histogram) ----
    unsigned bLo = kT, bThr = kT;              // default: every candidate wins
    if (C > need) {
        unsigned winB = kT;
        unsigned span = 0x7F800001u - kT;
        int sh;
        if (kT == 0x3FF33333u) sh = 17;        // tuned: boundary bin ~20 elems
        else { int t = 32 - __clz(span - 1u) - 8; sh = (t < 0) ? 0 : t; }

        for (int r = 0; r < 6; r++) {
            for (unsigned p = tid; p < C; p += NT) {
                unsigned d = (unsigned)(cand[p] >> 32) - winB;
                if (d < span) {
                    unsigned b = d >> sh;
                    if (b > 255u) b = 255u;
                    atomicAdd(&hist[b], 1u);
                }
            }
            __syncthreads();
            if (wid == 0) {                    // suffix sums + boundary find
                uint4 a = *(uint4*)&hist[8 * lane];
                uint4 b = *(uint4*)&hist[8 * lane + 4];
                unsigned s7 = b.w, s6 = b.z + s7, s5 = b.y + s6, s4 = b.x + s5;
                unsigned s3 = a.w + s4, s2 = a.z + s3, s1 = a.y + s2, s0 = a.x + s1;
                unsigned suf = s0;
                #pragma unroll
                for (int d = 1; d < 32; d <<= 1) {
                    unsigned n = __shfl_down_sync(0xFFFFFFFFu, suf, d);
                    if (lane + d < 32) suf += n;
                }
                unsigned add = suf - s0;
                unsigned sv[8] = { s0, s1, s2, s3, s4, s5, s6, s7 };
                #pragma unroll
                for (int i = 0; i < 8; i++) {
                    unsigned Sv = sv[i] + add;
                    unsigned Sn = (i < 7) ? (sv[i + 1] + add) : add;
                    if (Sv >= need && Sn < need) { S[3] = 8u*lane + i; S[4] = Sn; S[5] = Sv - Sn; }
                }
            }
            __syncthreads();
            unsigned jbin = S[3], nab = S[4], cnt_in = S[5];
            bool clamped = ((span - 1u) >> sh) > 255u;
            unsigned newLo = winB + (jbin << sh);
            unsigned newSpan = (clamped && jbin == 255u) ? (span - (255u << sh)) : (1u << sh);
            need -= nab;
            if (cnt_in <= 32u || sh == 0) { bLo = newLo; bThr = newLo + newSpan; break; }
            winB = newLo; span = newSpan;
            int t = 32 - __clz(newSpan - 1u) - 8;
            sh = (t < 0) ? 0 : t;
            if (tid < 256) hist[tid] = 0;
            __syncthreads();
        }
    }

    // ---- final pass over candidates: scatter sure winners, gather window ----
    for (unsigned p = tid; p < C; p += NT) {
        u64 ck = cand[p];
        unsigned bits = (unsigned)(ck >> 32);
        if (bits >= bThr) {
            orow[~(unsigned)ck] = __uint_as_float(bits);   // positive -> relu identity
        } else if (bits >= bLo) {
            unsigned q = atomicAdd(&S[2], 1u);
            if (q < WCAP) slist[q] = ck;
        }
    }
    __syncthreads();
    unsigned m = S[2]; if (m > WCAP) m = WCAP;

    // ---- exact stable rank on tiny boundary window (key desc, index asc) ----
    for (unsigned p = tid; p < m; p += NT) {
        u64 mine = slist[p];
        unsigned rk = 0;
        for (unsigned q = 0; q < m; q++) rk += (slist[q] > mine);
        if (rk < need)
            orow[~(unsigned)mine] = __uint_as_float((unsigned)(mine >> 32));
    }
}

extern "C" void kernel_launch(void* const* d_in, const int* in_sizes, int n_in,
                              void* d_out, int out_size) {
    const float* x = (const float*)d_in[0];
    float* out = (float*)d_out;
    int rows = in_sizes[0] / COLS;
    topk_kernel<<<rows, NT>>>(x, out);
}

// round 9
// speedup vs baseline: 1.0878x; 1.0878x over previous
#include <cuda_runtime.h>
#include <cstdint>

#define COLS 16384
#define KSEL 256
#define NT   512
#define WCAP 512

typedef unsigned long long u64;

__global__ void __launch_bounds__(NT, 3)
topk_kernel(const float* __restrict__ x, float* __restrict__ out)
{
    __shared__ unsigned hist[256];
    __shared__ u64 slist[WCAP];
    __shared__ unsigned S[8];   // 2:m 3:jbin 4:nab 5:cnt_in 6:total

    const int tid = threadIdx.x, lane = tid & 31, wid = tid >> 5;
    const size_t row = blockIdx.x;
    const float4* __restrict__ xr4 = (const float4*)(x + row * COLS);
    float* __restrict__ orow = out + row * COLS;
    float4* __restrict__ orow4 = (float4*)orow;

    if (tid < 256) hist[tid] = 0;
    if (tid == 0) S[2] = 0;
    __syncthreads();

    // ---- selection window in positive-float-bits space ----
    unsigned winB = 0x3FF33333u;            // bits(1.9f): ~470 expected for N(0,1)
    unsigned span = 0x7F800001u - winB;     // through +inf (top bin clamped)
    int      sh   = 17;                     // boundary bin ~20 elems expected
    unsigned need = KSEL;
    unsigned bLo = 0xFFFFFFFFu, bThr = 0xFFFFFFFFu;
    bool fellback = false;

    for (int r = 0; r < 10; r++) {
        // ---- stream the row; histogram candidates only (r=0: DRAM, r>0: L2) ----
        #pragma unroll 1
        for (int ch = 0; ch < 2; ch++) {
            float4 t[4];
            #pragma unroll
            for (int c = 0; c < 4; c++) t[c] = xr4[tid + (ch * 4 + c) * NT];
            #pragma unroll
            for (int c = 0; c < 4; c++) {
                unsigned b0 = __float_as_uint(t[c].x) - winB;
                unsigned b1 = __float_as_uint(t[c].y) - winB;
                unsigned b2 = __float_as_uint(t[c].z) - winB;
                unsigned b3 = __float_as_uint(t[c].w) - winB;
                if (b0 < span) atomicAdd(&hist[min(b0 >> sh, 255u)], 1u);
                if (b1 < span) atomicAdd(&hist[min(b1 >> sh, 255u)], 1u);
                if (b2 < span) atomicAdd(&hist[min(b2 >> sh, 255u)], 1u);
                if (b3 < span) atomicAdd(&hist[min(b3 >> sh, 255u)], 1u);
            }
        }
        __syncthreads();

        // ---- warp0: suffix sums over 256 bins + boundary find ----
        if (wid == 0) {
            uint4 a = *(uint4*)&hist[8 * lane];
            uint4 b = *(uint4*)&hist[8 * lane + 4];
            unsigned s7 = b.w, s6 = b.z + s7, s5 = b.y + s6, s4 = b.x + s5;
            unsigned s3 = a.w + s4, s2 = a.z + s3, s1 = a.y + s2, s0 = a.x + s1;
            unsigned suf = s0;
            #pragma unroll
            for (int d = 1; d < 32; d <<= 1) {
                unsigned n = __shfl_down_sync(0xFFFFFFFFu, suf, d);
                if (lane + d < 32) suf += n;
            }
            if (lane == 0) S[6] = suf;
            unsigned add = suf - s0;
            unsigned sv[8] = { s0, s1, s2, s3, s4, s5, s6, s7 };
            #pragma unroll
            for (int i = 0; i < 8; i++) {
                unsigned Sv = sv[i] + add;
                unsigned Sn = (i < 7) ? (sv[i + 1] + add) : add;
                if (Sv >= need && Sn < need) { S[3] = 8u*lane + i; S[4] = Sn; S[5] = Sv - Sn; }
            }
        }
        __syncthreads();

        unsigned C = S[6];
        if (C < need && !fellback) {
            // <256 above 1.9: re-histogram over ALL positives (L2-hot).
            // Non-positive top-K entries ReLU to 0 == background -> invisible,
            // so positives-only selection is exact.
            fellback = true;
            winB = 1u; span = 0x7F800000u; sh = 23;
            if (tid < 256) hist[tid] = 0;
            __syncthreads();
            continue;
        }
        if (C <= need) { bLo = winB; bThr = winB; break; }  // every candidate wins

        unsigned jbin = S[3], nab = S[4], cnt_in = S[5];
        bool clamped = ((span - 1u) >> sh) > 255u;
        unsigned newLo = winB + (jbin << sh);
        unsigned newSpan = (clamped && jbin == 255u) ? (span - (255u << sh)) : (1u << sh);
        need -= nab;
        if (cnt_in <= 32u || sh == 0) { bLo = newLo; bThr = newLo + newSpan; break; }
        winB = newLo; span = newSpan;                 // rare: refine from L2
        int t = 32 - __clz(newSpan - 1u) - 8;
        sh = (t < 0) ? 0 : t;
        if (tid < 256) hist[tid] = 0;
        __syncthreads();
    }

    // ---- pass 2 (L2-hot): fused select/zero write + boundary-window gather ----
    const unsigned thrSpan = 0x80000000u - bThr;  // [bThr, +inf-bits]: positive & selected
    const unsigned winSpan = bThr - bLo;
    #pragma unroll 1
    for (int ch = 0; ch < 2; ch++) {
        float4 t[4];
        #pragma unroll
        for (int c = 0; c < 4; c++) t[c] = xr4[tid + (ch * 4 + c) * NT];
        #pragma unroll
        for (int c = 0; c < 4; c++) {
            float f[4] = { t[c].x, t[c].y, t[c].z, t[c].w };
            float vv[4];
            unsigned idx0 = 4u * (unsigned)(tid + (ch * 4 + c) * NT);
            #pragma unroll
            for (int e = 0; e < 4; e++) {
                unsigned bits = __float_as_uint(f[e]);
                vv[e] = ((bits - bThr) < thrSpan) ? f[e] : 0.0f;
                if ((bits - bLo) < winSpan) {         // rare boundary element
                    unsigned p = atomicAdd(&S[2], 1u);
                    if (p < WCAP) slist[p] = ((u64)bits << 32) | (unsigned)~(idx0 + e);
                }
            }
            orow4[tid + (ch * 4 + c) * NT] = make_float4(vv[0], vv[1], vv[2], vv[3]);
        }
    }
    __syncthreads();

    // ---- exact stable rank on tiny boundary window (key desc, index asc) ----
    unsigned m = S[2]; if (m > WCAP) m = WCAP;
    for (unsigned p = tid; p < m; p += NT) {
        u64 mine = slist[p];
        unsigned rk = 0;
        for (unsigned q = 0; q < m; q++) rk += (slist[q] > mine);
        if (rk < need)
            orow[~(unsigned)mine] = __uint_as_float((unsigned)(mine >> 32));
    }
}

extern "C" void kernel_launch(void* const* d_in, const int* in_sizes, int n_in,
                              void* d_out, int out_size) {
    const float* x = (const float*)d_in[0];
    float* out = (float*)d_out;
    int rows = in_sizes[0] / COLS;
    topk_kernel<<<rows, NT>>>(x, out);
}

// round 10
// speedup vs baseline: 1.1132x; 1.0233x over previous
#include <cuda_runtime.h>
#include <cstdint>

#define COLS 16384
#define KSEL 256
#define NT   512
#define WCAP 512
#define ROWBYTES (COLS * 4)

// dynamic smem layout
#define OFF_SLIST 65536
#define OFF_HIST  (OFF_SLIST + WCAP * 8)   // 69632
#define OFF_S     (OFF_HIST + 1024)        // 70656
#define OFF_MBAR  (OFF_S + 32)             // 70688
#define SMEM_TOTAL (OFF_MBAR + 32)         // 70720 -> 3 CTAs/SM (212 KB < 227 KB)

typedef unsigned long long u64;

__device__ __forceinline__ unsigned smem_u32(const void* p) {
    unsigned r;
    asm("{ .reg .u64 t; cvta.to.shared.u64 t, %1; cvt.u32.u64 %0, t; }" : "=r"(r) : "l"(p));
    return r;
}
__device__ __forceinline__ void mbar_wait(unsigned mbar, unsigned phase) {
    asm volatile(
        "{\n\t.reg .pred P;\n\t"
        "W%=:\n\t"
        "mbarrier.try_wait.parity.acquire.cta.shared::cta.b64 P, [%0], %1, 0x989680;\n\t"
        "@P bra.uni D%=;\n\t"
        "bra.uni W%=;\n\t"
        "D%=:\n\t}"
        :: "r"(mbar), "r"(phase) : "memory");
}

extern __shared__ char smem[];

__global__ void __launch_bounds__(NT, 3)
topk_kernel(const float* __restrict__ x, float* __restrict__ out)
{
    u64*      slist = (u64*)(smem + OFF_SLIST);
    unsigned* hist  = (unsigned*)(smem + OFF_HIST);
    unsigned* S     = (unsigned*)(smem + OFF_S);   // 2:m 3:jbin 4:nab 5:cnt_in 6:total
    const unsigned mbar = smem_u32(smem + OFF_MBAR);
    const float4* s4 = (const float4*)smem;        // row buffer at offset 0

    const int tid = threadIdx.x, lane = tid & 31, wid = tid >> 5;
    const size_t row = blockIdx.x;
    float* __restrict__ orow = out + row * COLS;
    float4* __restrict__ orow4 = (float4*)orow;

    if (tid < 256) hist[tid] = 0;
    if (tid == 0) {
        S[2] = 0;
        asm volatile("mbarrier.init.shared.b64 [%0], 1;" :: "r"(mbar) : "memory");
    }
    __syncthreads();

    // ---- one TMA bulk load: the whole row, engine-paced ----
    if (tid == 0) {
        asm volatile("fence.proxy.async.shared::cta;" ::: "memory");
        asm volatile("mbarrier.arrive.expect_tx.shared.b64 _, [%0], %1;"
                     :: "r"(mbar), "n"(ROWBYTES) : "memory");
        asm volatile("cp.async.bulk.shared::cluster.global.mbarrier::complete_tx::bytes [%0], [%1], %2, [%3];"
                     :: "r"(smem_u32(smem)), "l"(x + row * COLS), "n"(ROWBYTES), "r"(mbar) : "memory");
    }
    mbar_wait(mbar, 0);

    // ---- selection window in positive-float-bits space ----
    unsigned winB = 0x3FF33333u;            // bits(1.9f): ~470 expected for N(0,1)
    unsigned span = 0x7F800001u - winB;     // through +inf (top bin clamped)
    int      sh   = 17;                     // boundary bin ~20 elems expected
    unsigned need = KSEL;
    unsigned bLo = 0xFFFFFFFFu, bThr = 0xFFFFFFFFu;
    bool fellback = false;

    for (int r = 0; r < 10; r++) {
        // ---- stream the row from smem; histogram candidates only ----
        #pragma unroll 1
        for (int ch = 0; ch < 2; ch++) {
            float4 t[4];
            #pragma unroll
            for (int c = 0; c < 4; c++) t[c] = s4[tid + (ch * 4 + c) * NT];
            #pragma unroll
            for (int c = 0; c < 4; c++) {
                unsigned b0 = __float_as_uint(t[c].x) - winB;
                unsigned b1 = __float_as_uint(t[c].y) - winB;
                unsigned b2 = __float_as_uint(t[c].z) - winB;
                unsigned b3 = __float_as_uint(t[c].w) - winB;
                if (b0 < span) atomicAdd(&hist[min(b0 >> sh, 255u)], 1u);
                if (b1 < span) atomicAdd(&hist[min(b1 >> sh, 255u)], 1u);
                if (b2 < span) atomicAdd(&hist[min(b2 >> sh, 255u)], 1u);
                if (b3 < span) atomicAdd(&hist[min(b3 >> sh, 255u)], 1u);
            }
        }
        __syncthreads();

        // ---- warp0: suffix sums over 256 bins + boundary find ----
        if (wid == 0) {
            uint4 a = *(uint4*)&hist[8 * lane];
            uint4 b = *(uint4*)&hist[8 * lane + 4];
            unsigned s7 = b.w, s6 = b.z + s7, s5 = b.y + s6, s4v = b.x + s5;
            unsigned s3 = a.w + s4v, s2 = a.z + s3, s1 = a.y + s2, s0 = a.x + s1;
            unsigned suf = s0;
            #pragma unroll
            for (int d = 1; d < 32; d <<= 1) {
                unsigned n = __shfl_down_sync(0xFFFFFFFFu, suf, d);
                if (lane + d < 32) suf += n;
            }
            if (lane == 0) S[6] = suf;
            unsigned add = suf - s0;
            unsigned sv[8] = { s0, s1, s2, s3, s4v, s5, s6, s7 };
            #pragma unroll
            for (int i = 0; i < 8; i++) {
                unsigned Sv = sv[i] + add;
                unsigned Sn = (i < 7) ? (sv[i + 1] + add) : add;
                if (Sv >= need && Sn < need) { S[3] = 8u*lane + i; S[4] = Sn; S[5] = Sv - Sn; }
            }
        }
        __syncthreads();

        unsigned C = S[6];
        if (C < need && !fellback) {
            // <256 above 1.9: re-histogram over ALL positives (smem-hot).
            // Non-positive top-K entries ReLU to 0 == background -> invisible,
            // so positives-only selection is exact.
            fellback = true;
            winB = 1u; span = 0x7F800000u; sh = 23;
            if (tid < 256) hist[tid] = 0;
            __syncthreads();
            continue;
        }
        if (C <= need) { bLo = winB; bThr = winB; break; }  // every candidate wins

        unsigned jbin = S[3], nab = S[4], cnt_in = S[5];
        bool clamped = ((span - 1u) >> sh) > 255u;
        unsigned newLo = winB + (jbin << sh);
        unsigned newSpan = (clamped && jbin == 255u) ? (span - (255u << sh)) : (1u << sh);
        need -= nab;
        if (cnt_in <= 32u || sh == 0) { bLo = newLo; bThr = newLo + newSpan; break; }
        winB = newLo; span = newSpan;                 // rare: refine from smem
        int t = 32 - __clz(newSpan - 1u) - 8;
        sh = (t < 0) ? 0 : t;
        if (tid < 256) hist[tid] = 0;
        __syncthreads();
    }

    // ---- pass 2 (smem-hot): fused select/zero write + boundary-window gather ----
    const unsigned thrSpan = 0x80000000u - bThr;  // [bThr, +inf-bits]: positive & selected
    const unsigned winSpan = bThr - bLo;
    #pragma unroll 1
    for (int ch = 0; ch < 2; ch++) {
        float4 t[4];
        #pragma unroll
        for (int c = 0; c < 4; c++) t[c] = s4[tid + (ch * 4 + c) * NT];
        #pragma unroll
        for (int c = 0; c < 4; c++) {
            float f[4] = { t[c].x, t[c].y, t[c].z, t[c].w };
            float vv[4];
            unsigned idx0 = 4u * (unsigned)(tid + (ch * 4 + c) * NT);
            #pragma unroll
            for (int e = 0; e < 4; e++) {
                unsigned bits = __float_as_uint(f[e]);
                vv[e] = ((bits - bThr) < thrSpan) ? f[e] : 0.0f;
                if ((bits - bLo) < winSpan) {         // rare boundary element
                    unsigned p = atomicAdd(&S[2], 1u);
                    if (p < WCAP) slist[p] = ((u64)bits << 32) | (unsigned)~(idx0 + e);
                }
            }
            orow4[tid + (ch * 4 + c) * NT] = make_float4(vv[0], vv[1], vv[2], vv[3]);
        }
    }
    __syncthreads();

    // ---- exact stable rank on tiny boundary window (key desc, index asc) ----
    unsigned m = S[2]; if (m > WCAP) m = WCAP;
    for (unsigned p = tid; p < m; p += NT) {
        u64 mine = slist[p];
        unsigned rk = 0;
        for (unsigned q = 0; q < m; q++) rk += (slist[q] > mine);
        if (rk < need)
            orow[~(unsigned)mine] = __uint_as_float((unsigned)(mine >> 32));
    }
}

extern "C" void kernel_launch(void* const* d_in, const int* in_sizes, int n_in,
                              void* d_out, int out_size) {
    const float* x = (const float*)d_in[0];
    float* out = (float*)d_out;
    int rows = in_sizes[0] / COLS;
    cudaFuncSetAttribute(topk_kernel, cudaFuncAttributeMaxDynamicSharedMemorySize, SMEM_TOTAL);
    topk_kernel<<<rows, NT, SMEM_TOTAL>>>(x, out);
}

// round 11
// speedup vs baseline: 1.1139x; 1.0006x over previous
#include <cuda_runtime.h>
#include <cstdint>

#define COLS 16384
#define KSEL 256
#define NT   512
#define WCAP 512
#define ROWBYTES (COLS * 4)

// dynamic smem layout
#define OFF_SLIST 65536
#define OFF_HIST  (OFF_SLIST + WCAP * 8)   // 69632
#define OFF_S     (OFF_HIST + 1024)        // 70656
#define OFF_MBAR  (OFF_S + 32)             // 70688
#define SMEM_TOTAL (OFF_MBAR + 32)         // 70720 -> 3 CTAs/SM (212 KB < 227 KB)

typedef unsigned long long u64;

__device__ __forceinline__ unsigned smem_u32(const void* p) {
    unsigned r;
    asm("{ .reg .u64 t; cvta.to.shared.u64 t, %1; cvt.u32.u64 %0, t; }" : "=r"(r) : "l"(p));
    return r;
}
__device__ __forceinline__ void mbar_wait(unsigned mbar, unsigned phase) {
    asm volatile(
        "{\n\t.reg .pred P;\n\t"
        "W%=:\n\t"
        "mbarrier.try_wait.parity.acquire.cta.shared::cta.b64 P, [%0], %1, 0x989680;\n\t"
        "@P bra.uni D%=;\n\t"
        "bra.uni W%=;\n\t"
        "D%=:\n\t}"
        :: "r"(mbar), "r"(phase) : "memory");
}

extern __shared__ char smem[];

__global__ void __launch_bounds__(NT, 3)
topk_kernel(const float* __restrict__ x, float* __restrict__ out)
{
    u64*      slist = (u64*)(smem + OFF_SLIST);
    unsigned* hist  = (unsigned*)(smem + OFF_HIST);
    unsigned* S     = (unsigned*)(smem + OFF_S);   // 2:m 3:jbin 4:nab 5:cnt_in 6:total
    const unsigned mbar = smem_u32(smem + OFF_MBAR);
    float4*  s4 = (float4*)smem;                   // row buffer at offset 0
    float*   sf = (float*)smem;

    const int tid = threadIdx.x, lane = tid & 31, wid = tid >> 5;
    const size_t row = blockIdx.x;
    float* __restrict__ orow = out + row * COLS;

    // ---- tid0: init + TMA load, straight-line (no sync needed before issue) ----
    if (tid == 0) {
        S[2] = 0;
        asm volatile("mbarrier.init.shared.b64 [%0], 1;" :: "r"(mbar) : "memory");
        asm volatile("fence.proxy.async.shared::cta;" ::: "memory");
        asm volatile("mbarrier.arrive.expect_tx.shared.b64 _, [%0], %1;"
                     :: "r"(mbar), "n"(ROWBYTES) : "memory");
        asm volatile("cp.async.bulk.shared::cluster.global.mbarrier::complete_tx::bytes [%0], [%1], %2, [%3];"
                     :: "r"(smem_u32(smem)), "l"(x + row * COLS), "n"(ROWBYTES), "r"(mbar) : "memory");
    }
    if (tid < 256) hist[tid] = 0;
    __syncthreads();      // mbar init visible to all waiters; hist/S ready
    mbar_wait(mbar, 0);

    // ---- selection window in positive-float-bits space ----
    unsigned winB = 0x3FF33333u;            // bits(1.9f): ~470 expected for N(0,1)
    unsigned span = 0x7F800001u - winB;     // through +inf (top bin clamped)
    int      sh   = 17;                     // boundary bin ~20 elems expected
    unsigned need = KSEL;
    unsigned bLo = 0xFFFFFFFFu, bThr = 0xFFFFFFFFu;
    bool fellback = false;

    for (int r = 0; r < 10; r++) {
        // ---- stream the row from smem; histogram candidates only ----
        #pragma unroll 1
        for (int ch = 0; ch < 2; ch++) {
            float4 t[4];
            #pragma unroll
            for (int c = 0; c < 4; c++) t[c] = s4[tid + (ch * 4 + c) * NT];
            #pragma unroll
            for (int c = 0; c < 4; c++) {
                unsigned b0 = __float_as_uint(t[c].x) - winB;
                unsigned b1 = __float_as_uint(t[c].y) - winB;
                unsigned b2 = __float_as_uint(t[c].z) - winB;
                unsigned b3 = __float_as_uint(t[c].w) - winB;
                if (b0 < span) atomicAdd(&hist[min(b0 >> sh, 255u)], 1u);
                if (b1 < span) atomicAdd(&hist[min(b1 >> sh, 255u)], 1u);
                if (b2 < span) atomicAdd(&hist[min(b2 >> sh, 255u)], 1u);
                if (b3 < span) atomicAdd(&hist[min(b3 >> sh, 255u)], 1u);
            }
        }
        __syncthreads();

        // ---- warp0: suffix sums over 256 bins + boundary find ----
        if (wid == 0) {
            uint4 a = *(uint4*)&hist[8 * lane];
            uint4 b = *(uint4*)&hist[8 * lane + 4];
            unsigned s7 = b.w, s6 = b.z + s7, s5 = b.y + s6, s4v = b.x + s5;
            unsigned s3 = a.w + s4v, s2 = a.z + s3, s1 = a.y + s2, s0 = a.x + s1;
            unsigned suf = s0;
            #pragma unroll
            for (int d = 1; d < 32; d <<= 1) {
                unsigned n = __shfl_down_sync(0xFFFFFFFFu, suf, d);
                if (lane + d < 32) suf += n;
            }
            if (lane == 0) S[6] = suf;
            unsigned add = suf - s0;
            unsigned sv[8] = { s0, s1, s2, s3, s4v, s5, s6, s7 };
            #pragma unroll
            for (int i = 0; i < 8; i++) {
                unsigned Sv = sv[i] + add;
                unsigned Sn = (i < 7) ? (sv[i + 1] + add) : add;
                if (Sv >= need && Sn < need) { S[3] = 8u*lane + i; S[4] = Sn; S[5] = Sv - Sn; }
            }
        }
        __syncthreads();

        unsigned C = S[6];
        if (C < need && !fellback) {
            // <256 above 1.9: re-histogram over ALL positives (smem-hot).
            // Non-positive top-K entries ReLU to 0 == background -> invisible,
            // so positives-only selection is exact.
            fellback = true;
            winB = 1u; span = 0x7F800000u; sh = 23;
            if (tid < 256) hist[tid] = 0;
            __syncthreads();
            continue;
        }
        if (C <= need) { bLo = winB; bThr = winB; break; }  // every candidate wins

        unsigned jbin = S[3], nab = S[4], cnt_in = S[5];
        bool clamped = ((span - 1u) >> sh) > 255u;
        unsigned newLo = winB + (jbin << sh);
        unsigned newSpan = (clamped && jbin == 255u) ? (span - (255u << sh)) : (1u << sh);
        need -= nab;
        if (cnt_in <= 32u || sh == 0) { bLo = newLo; bThr = newLo + newSpan; break; }
        winB = newLo; span = newSpan;                 // rare: refine from smem
        int t = 32 - __clz(newSpan - 1u) - 8;
        sh = (t < 0) ? 0 : t;
        if (tid < 256) hist[tid] = 0;
        __syncthreads();
    }

    // ---- pass 2: in-place select/zero in SMEM + boundary-window gather ----
    const unsigned thrSpan = 0x80000000u - bThr;  // [bThr, +inf-bits]: positive & selected
    const unsigned winSpan = bThr - bLo;
    #pragma unroll 1
    for (int ch = 0; ch < 2; ch++) {
        float4 t[4];
        #pragma unroll
        for (int c = 0; c < 4; c++) t[c] = s4[tid + (ch * 4 + c) * NT];
        #pragma unroll
        for (int c = 0; c < 4; c++) {
            float f[4] = { t[c].x, t[c].y, t[c].z, t[c].w };
            float vv[4];
            unsigned idx0 = 4u * (unsigned)(tid + (ch * 4 + c) * NT);
            #pragma unroll
            for (int e = 0; e < 4; e++) {
                unsigned bits = __float_as_uint(f[e]);
                vv[e] = ((bits - bThr) < thrSpan) ? f[e] : 0.0f;
                if ((bits - bLo) < winSpan) {         // rare boundary element
                    unsigned p = atomicAdd(&S[2], 1u);
                    if (p < WCAP) slist[p] = ((u64)bits << 32) | (unsigned)~(idx0 + e);
                }
            }
            s4[tid + (ch * 4 + c) * NT] = make_float4(vv[0], vv[1], vv[2], vv[3]);
        }
    }
    __syncthreads();

    // ---- exact stable rank on tiny boundary window; winners into SMEM row ----
    unsigned m = S[2]; if (m > WCAP) m = WCAP;
    for (unsigned p = tid; p < m; p += NT) {
        u64 mine = slist[p];
        unsigned rk = 0;
        for (unsigned q = 0; q < m; q++) rk += (slist[q] > mine);
        if (rk < need)
            sf[~(unsigned)mine] = __uint_as_float((unsigned)(mine >> 32));
    }
    __syncthreads();

    // ---- one TMA bulk store: the whole finished row, engine-paced ----
    if (tid == 0) {
        asm volatile("fence.proxy.async.shared::cta;" ::: "memory");
        asm volatile("cp.async.bulk.global.shared::cta.bulk_group [%0], [%1], %2;"
                     :: "l"(orow), "r"(smem_u32(smem)), "n"(ROWBYTES) : "memory");
        asm volatile("cp.async.bulk.commit_group;" ::: "memory");
        asm volatile("cp.async.bulk.wait_group 0;" ::: "memory");
    }
}

extern "C" void kernel_launch(void* const* d_in, const int* in_sizes, int n_in,
                              void* d_out, int out_size) {
    const float* x = (const float*)d_in[0];
    float* out = (float*)d_out;
    int rows = in_sizes[0] / COLS;
    cudaFuncSetAttribute(topk_kernel, cudaFuncAttributeMaxDynamicSharedMemorySize, SMEM_TOTAL);
    topk_kernel<<<rows, NT, SMEM_TOTAL>>>(x, out);
}

// round 12
// speedup vs baseline: 1.1203x; 1.0058x over previous
#include <cuda_runtime.h>
#include <cstdint>

#define COLS 16384
#define KSEL 256
#define NT   512
#define WCAP 512
#define ROWBYTES (COLS * 4)
#define NCH  4
#define CHBYTES (ROWBYTES / NCH)   // 16384
#define CHF4    (CHBYTES / 16)     // 1024 float4 per chunk
#define CHELEM  (CHBYTES / 4)      // 4096 floats per chunk

// dynamic smem layout
#define OFF_SLIST 65536
#define OFF_HIST  (OFF_SLIST + WCAP * 8)   // 69632
#define OFF_S     (OFF_HIST + 1024)        // 70656
#define OFF_MBAR  (OFF_S + 32)             // 70688
#define SMEM_TOTAL (OFF_MBAR + NCH * 8)    // 70720 -> 3 CTAs/SM

typedef unsigned long long u64;

__device__ __forceinline__ unsigned smem_u32(const void* p) {
    unsigned r;
    asm("{ .reg .u64 t; cvta.to.shared.u64 t, %1; cvt.u32.u64 %0, t; }" : "=r"(r) : "l"(p));
    return r;
}
__device__ __forceinline__ void mbar_wait(unsigned mbar, unsigned phase) {
    asm volatile(
        "{\n\t.reg .pred P;\n\t"
        "W%=:\n\t"
        "mbarrier.try_wait.parity.acquire.cta.shared::cta.b64 P, [%0], %1, 0x989680;\n\t"
        "@P bra.uni D%=;\n\t"
        "bra.uni W%=;\n\t"
        "D%=:\n\t}"
        :: "r"(mbar), "r"(phase) : "memory");
}

extern __shared__ char smem[];

__global__ void __launch_bounds__(NT, 3)
topk_kernel(const float* __restrict__ x, float* __restrict__ out)
{
    u64*      slist = (u64*)(smem + OFF_SLIST);
    unsigned* hist  = (unsigned*)(smem + OFF_HIST);
    unsigned* S     = (unsigned*)(smem + OFF_S);   // 2:m 3:jbin 4:nab 5:cnt_in 6:total
    const unsigned mb0 = smem_u32(smem + OFF_MBAR);
    float4* s4 = (float4*)smem;
    float*  sf = (float*)smem;

    const int tid = threadIdx.x, lane = tid & 31, wid = tid >> 5;
    const size_t row = blockIdx.x;
    const float* __restrict__ xrow = x + row * COLS;
    float* __restrict__ orow = out + row * COLS;

    // ---- tid0: init mbarriers + issue ALL 4 chunked TMA loads upfront ----
    if (tid == 0) {
        S[2] = 0;
        #pragma unroll
        for (int ch = 0; ch < NCH; ch++)
            asm volatile("mbarrier.init.shared.b64 [%0], 1;" :: "r"(mb0 + ch * 8) : "memory");
        asm volatile("fence.proxy.async.shared::cta;" ::: "memory");
        #pragma unroll
        for (int ch = 0; ch < NCH; ch++) {
            asm volatile("mbarrier.arrive.expect_tx.shared.b64 _, [%0], %1;"
                         :: "r"(mb0 + ch * 8), "n"(CHBYTES) : "memory");
            asm volatile("cp.async.bulk.shared::cluster.global.mbarrier::complete_tx::bytes [%0], [%1], %2, [%3];"
                         :: "r"(smem_u32(smem) + ch * CHBYTES), "l"(xrow + ch * CHELEM),
                            "n"(CHBYTES), "r"(mb0 + ch * 8) : "memory");
        }
    }
    if (tid < 256) hist[tid] = 0;
    __syncthreads();

    // ---- pass 1: per-chunk wait + histogram (overlaps remaining loads) ----
    const unsigned winB0 = 0x3FF33333u;     // bits(1.9f): ~470 expected for N(0,1)
    const unsigned span0 = 0x7F800001u - winB0;
    unsigned cmask = 0;                      // bit per owned element that is >= 1.9
    #pragma unroll
    for (int ch = 0; ch < NCH; ch++) {
        mbar_wait(mb0 + ch * 8, 0);
        #pragma unroll
        for (int c = 0; c < 2; c++) {
            float4 t = s4[ch * CHF4 + c * NT + tid];
            unsigned bb[4] = { __float_as_uint(t.x) - winB0, __float_as_uint(t.y) - winB0,
                               __float_as_uint(t.z) - winB0, __float_as_uint(t.w) - winB0 };
            #pragma unroll
            for (int e = 0; e < 4; e++) {
                if (bb[e] < span0) {
                    atomicAdd(&hist[min(bb[e] >> 17, 255u)], 1u);
                    cmask |= 1u << (ch * 8 + c * 4 + e);
                }
            }
        }
    }
    __syncthreads();

    // ---- narrowing loop (round 0 reuses pass-1 hist) ----
    unsigned winB = winB0, span = span0;
    int sh = 17;
    unsigned need = KSEL;
    unsigned bLo = 0xFFFFFFFFu, bThr = 0xFFFFFFFFu;
    bool fellback = false, maskvalid = true;

    for (int r = 0; r < 10; r++) {
        if (r > 0) {   // re-histogram full row from smem (rare paths)
            #pragma unroll 1
            for (int i = 0; i < 8; i++) {
                float4 t = s4[tid + i * NT];
                unsigned b0 = __float_as_uint(t.x) - winB, b1 = __float_as_uint(t.y) - winB;
                unsigned b2 = __float_as_uint(t.z) - winB, b3 = __float_as_uint(t.w) - winB;
                if (b0 < span) atomicAdd(&hist[min(b0 >> sh, 255u)], 1u);
                if (b1 < span) atomicAdd(&hist[min(b1 >> sh, 255u)], 1u);
                if (b2 < span) atomicAdd(&hist[min(b2 >> sh, 255u)], 1u);
                if (b3 < span) atomicAdd(&hist[min(b3 >> sh, 255u)], 1u);
            }
            __syncthreads();
        }
        // warp0: suffix sums over 256 bins + boundary find
        if (wid == 0) {
            uint4 a = *(uint4*)&hist[8 * lane];
            uint4 b = *(uint4*)&hist[8 * lane + 4];
            unsigned s7 = b.w, s6 = b.z + s7, s5 = b.y + s6, s4v = b.x + s5;
            unsigned s3 = a.w + s4v, s2 = a.z + s3, s1 = a.y + s2, s0 = a.x + s1;
            unsigned suf = s0;
            #pragma unroll
            for (int d = 1; d < 32; d <<= 1) {
                unsigned n = __shfl_down_sync(0xFFFFFFFFu, suf, d);
                if (lane + d < 32) suf += n;
            }
            if (lane == 0) S[6] = suf;
            unsigned add = suf - s0;
            unsigned sv[8] = { s0, s1, s2, s3, s4v, s5, s6, s7 };
            #pragma unroll
            for (int i = 0; i < 8; i++) {
                unsigned Sv = sv[i] + add;
                unsigned Sn = (i < 7) ? (sv[i + 1] + add) : add;
                if (Sv >= need && Sn < need) { S[3] = 8u*lane + i; S[4] = Sn; S[5] = Sv - Sn; }
            }
        }
        __syncthreads();

        unsigned C = S[6];
        if (C < need && !fellback) {
            // <256 above 1.9: re-histogram over ALL positives (exact: non-positive
            // top-K entries ReLU to 0 == background, invisible)
            fellback = true; maskvalid = false;
            winB = 1u; span = 0x7F800000u; sh = 23;
            if (tid < 256) hist[tid] = 0;
            __syncthreads();
            continue;
        }
        if (C <= need) { bLo = winB; bThr = winB; break; }  // every candidate wins

        unsigned jbin = S[3], nab = S[4], cnt_in = S[5];
        bool clamped = ((span - 1u) >> sh) > 255u;
        unsigned newLo = winB + (jbin << sh);
        unsigned newSpan = (clamped && jbin == 255u) ? (span - (255u << sh)) : (1u << sh);
        need -= nab;
        if (cnt_in <= 32u || sh == 0) { bLo = newLo; bThr = newLo + newSpan; break; }
        winB = newLo; span = newSpan;
        int t = 32 - __clz(newSpan - 1u) - 8;
        sh = (t < 0) ? 0 : t;
        if (tid < 256) hist[tid] = 0;
        __syncthreads();
    }

    // ---- pass 2a: gather boundary window (mask fast path: ~1 elem/thread) ----
    const unsigned winSpan = bThr - bLo;
    if (winSpan) {
        if (maskvalid) {   // bLo >= winB0 here, so mask is a superset of the window
            unsigned mrem = cmask;
            while (mrem) {
                int b = __ffs(mrem) - 1; mrem &= mrem - 1;
                int ch = b >> 3, c = (b >> 2) & 1, e = b & 3;
                unsigned idx = 4u * (unsigned)(ch * CHF4 + c * NT + tid) + (unsigned)e;
                unsigned bits = __float_as_uint(sf[idx]);
                if ((bits - bLo) < winSpan) {
                    unsigned p = atomicAdd(&S[2], 1u);
                    if (p < WCAP) slist[p] = ((u64)bits << 32) | (unsigned)~idx;
                }
            }
        } else {           // fallback window can sit below 1.9: full scan
            #pragma unroll 1
            for (int i = 0; i < 8; i++) {
                float4 t = s4[tid + i * NT];
                unsigned idx0 = 4u * (unsigned)(tid + i * NT);
                float f[4] = { t.x, t.y, t.z, t.w };
                #pragma unroll
                for (int e = 0; e < 4; e++) {
                    unsigned bits = __float_as_uint(f[e]);
                    if ((bits - bLo) < winSpan) {
                        unsigned p = atomicAdd(&S[2], 1u);
                        if (p < WCAP) slist[p] = ((u64)bits << 32) | (unsigned)~(idx0 + e);
                    }
                }
            }
        }
    }
    __syncthreads();

    // ---- rank BEFORE the output pass (m <= NT: at most one winner per thread) ----
    unsigned m = S[2]; if (m > WCAP) m = WCAP;
    unsigned rwidx = 0xFFFFFFFFu; float rwval = 0.0f;
    if ((unsigned)tid < m) {
        u64 mine = slist[tid];
        unsigned rk = 0;
        for (unsigned q = 0; q < m; q++) rk += (slist[q] > mine);
        if (rk < need) {   // key desc, index asc (low word is ~idx)
            rwidx = ~(unsigned)mine;
            rwval = __uint_as_float((unsigned)(mine >> 32));
        }
    }

    // ---- pass 2b: chunked select-write + pipelined TMA stores (1 chunk behind) ----
    const unsigned thrSpan = 0x80000000u - bThr;
    #pragma unroll 1
    for (int ch = 0; ch < NCH; ch++) {
        #pragma unroll
        for (int c = 0; c < 2; c++) {
            const int pos = ch * CHF4 + c * NT + tid;
            float4 t = s4[pos];
            float f[4] = { t.x, t.y, t.z, t.w };
            float vv[4];
            #pragma unroll
            for (int e = 0; e < 4; e++) {
                unsigned bits = __float_as_uint(f[e]);
                vv[e] = ((bits - bThr) < thrSpan) ? f[e] : 0.0f;
            }
            s4[pos] = make_float4(vv[0], vv[1], vv[2], vv[3]);
        }
        __syncthreads();   // select-writes of ch done; winner-scatter of ch-1 done
        if (tid == 0 && ch >= 1) {
            asm volatile("fence.proxy.async.shared::cta;" ::: "memory");
            asm volatile("cp.async.bulk.global.shared::cta.bulk_group [%0], [%1], %2;"
                         :: "l"(orow + (ch - 1) * CHELEM),
                            "r"(smem_u32(smem) + (ch - 1) * CHBYTES), "n"(CHBYTES) : "memory");
            asm volatile("cp.async.bulk.commit_group;" ::: "memory");
        }
        // scatter this chunk's boundary winner (if mine lives here)
        if (rwidx != 0xFFFFFFFFu && (rwidx >> 12) == (unsigned)ch)
            sf[rwidx] = rwval;
    }
    __syncthreads();       // last chunk's select-writes + winner scatter visible
    if (tid == 0) {
        asm volatile("fence.proxy.async.shared::cta;" ::: "memory");
        asm volatile("cp.async.bulk.global.shared::cta.bulk_group [%0], [%1], %2;"
                     :: "l"(orow + (NCH - 1) * CHELEM),
                        "r"(smem_u32(smem) + (NCH - 1) * CHBYTES), "n"(CHBYTES) : "memory");
        asm volatile("cp.async.bulk.commit_group;" ::: "memory");
        asm volatile("cp.async.bulk.wait_group 0;" ::: "memory");
    }
}

extern "C" void kernel_launch(void* const* d_in, const int* in_sizes, int n_in,
                              void* d_out, int out_size) {
    const float* x = (const float*)d_in[0];
    float* out = (float*)d_out;
    int rows = in_sizes[0] / COLS;
    cudaFuncSetAttribute(topk_kernel, cudaFuncAttributeMaxDynamicSharedMemorySize, SMEM_TOTAL);
    topk_kernel<<<rows, NT, SMEM_TOTAL>>>(x, out);
}